// round 1
// baseline (speedup 1.0000x reference)
#include <cuda_runtime.h>
#include <cuda_bf16.h>
#include <cstdint>

#define H 192
#define K2H 384
#define NNODES 504   // 256 leaves + 128 + 64 + 32 + 16 + 8

// Scratch (allocation-free rule: __device__ globals)
__device__ __nv_bfloat16 g_Vbf[(size_t)H * K2H * K2H];   // 54 MB bf16 copy of Vt
__device__ float g_nodes[NNODES * H];                     // all node vectors, fp32

// ---------------------------------------------------------------------------
// Kernel 1: convert Vt fp32 -> bf16
// ---------------------------------------------------------------------------
__global__ void convert_kernel(const float* __restrict__ Vt) {
    const size_t n4 = (size_t)H * K2H * K2H / 4;   // 7,077,888
    const float4* src = (const float4*)Vt;
    size_t stride = (size_t)gridDim.x * blockDim.x;
    for (size_t i = (size_t)blockIdx.x * blockDim.x + threadIdx.x; i < n4; i += stride) {
        float4 v = src[i];
        __nv_bfloat162 lo, hi;
        lo.x = __float2bfloat16_rn(v.x); lo.y = __float2bfloat16_rn(v.y);
        hi.x = __float2bfloat16_rn(v.z); hi.y = __float2bfloat16_rn(v.w);
        uint2 pk;
        pk.x = *(const unsigned*)&lo;
        pk.y = *(const unsigned*)&hi;
        *(uint2*)(g_Vbf + 4 * i) = pk;
    }
}

// ---------------------------------------------------------------------------
// Kernel 2: leaf embedding gather
// ---------------------------------------------------------------------------
__global__ void leaf_kernel(const float* __restrict__ embed, const int* __restrict__ leaf_ids) {
    int n = blockIdx.x;          // 0..255, row order matches reference reshape
    int t = threadIdx.x;         // 0..191
    g_nodes[n * H + t] = embed[(size_t)leaf_ids[n] * H + t];
}

// ---------------------------------------------------------------------------
// bf16 m16n8k16 mma
// ---------------------------------------------------------------------------
__device__ __forceinline__ void mma16816(float* d, const unsigned* a, unsigned b0, unsigned b1) {
    asm volatile(
        "mma.sync.aligned.m16n8k16.row.col.f32.bf16.bf16.f32 "
        "{%0,%1,%2,%3},{%4,%5,%6,%7},{%8,%9},{%0,%1,%2,%3};"
        : "+f"(d[0]), "+f"(d[1]), "+f"(d[2]), "+f"(d[3])
        : "r"(a[0]), "r"(a[1]), "r"(a[2]), "r"(a[3]), "r"(b0), "r"(b1));
}

// ---------------------------------------------------------------------------
// Kernel 3: one tree level. blockIdx.x = h (192 CTAs). 256 threads.
// Computes y[n] = tanh( c_n^T V_h c_n + (W c_n)_h + b_h ) for all N nodes.
// GEMM: U[x, n] = V_h[x, :] @ c[:, n], fused epilogue y[n] += sum_x c[n,x] U[x,n].
// NT = n-tiles per warp column; Npad = 16*NT.
// ---------------------------------------------------------------------------
#define AS_STR 392   // padded k-stride (bf16 elems): 4g+tg bank pattern -> conflict-free

template <int NT>
__global__ void __launch_bounds__(256, 1)
level_kernel(int prevBase, int prevN, int outBase, int Nlev,
             const float* __restrict__ W, const float* __restrict__ bias) {
    extern __shared__ char smraw[];
    __nv_bfloat16* As = (__nv_bfloat16*)smraw;         // [128][AS_STR]
    __nv_bfloat16* Bs = As + 128 * AS_STR;             // [Npad<=128][AS_STR]  (c vectors, k-major)
    float* ysm  = (float*)(Bs + 128 * AS_STR);         // [4][128] per-warp-row partials
    float* Wcol = ysm + 4 * 128;                       // [384]

    const int Npad = NT * 16;
    const int h = blockIdx.x;
    const int tid = threadIdx.x;

    for (int i = tid; i < 512; i += 256) ysm[i] = 0.f;
    for (int y = tid; y < K2H; y += 256) Wcol[y] = W[y * H + h];

    // Gather B operand: Bs[n][y] = c[n, y] = concat(child0, child1)
    const int npt = Nlev >> 3;   // nodes per tree this level (B=8 trees)
    for (int i = tid; i < Npad * K2H; i += 256) {
        int n = i / K2H, y = i - n * K2H;
        float v = 0.f;
        if (n < Nlev) {
            int bt = n / npt, j = n - bt * npt;
            int child = prevBase + bt * prevN + 2 * j + (y >= H);
            v = g_nodes[child * H + (y >= H ? y - H : y)];
        }
        Bs[n * AS_STR + y] = __float2bfloat16_rn(v);
    }

    const int warp = tid >> 5, lane = tid & 31;
    const int wm = warp >> 1, wn = warp & 1;       // 4 M-warps x 2 N-warps
    const int g = lane >> 2, tg = lane & 3;
    const int m0 = wm * 32;
    const int nb0 = wn * (Npad / 2);

    for (int xb = 0; xb < 3; xb++) {               // 3 M-blocks of 128 rows = 384 x-rows
        __syncthreads();                           // protect As reads of prev iter + Bs gather
        const uint4* src = (const uint4*)(g_Vbf + ((size_t)h * K2H + xb * 128) * K2H);
        for (int i = tid; i < 128 * 48; i += 256) {
            int m = i / 48, kq = i - m * 48;
            *(uint4*)(As + m * AS_STR + kq * 8) = src[m * 48 + kq];
        }
        __syncthreads();

        float acc[2][NT][4];
        #pragma unroll
        for (int mt = 0; mt < 2; mt++)
            #pragma unroll
            for (int nt = 0; nt < NT; nt++)
                #pragma unroll
                for (int q = 0; q < 4; q++) acc[mt][nt][q] = 0.f;

        #pragma unroll 4
        for (int ks = 0; ks < 24; ks++) {          // K = 384 = 24 * 16
            int k0 = ks * 16;
            unsigned a[2][4];
            #pragma unroll
            for (int mt = 0; mt < 2; mt++) {
                const __nv_bfloat16* Ar = As + (m0 + mt * 16 + g) * AS_STR + k0 + 2 * tg;
                a[mt][0] = *(const unsigned*)(Ar);
                a[mt][1] = *(const unsigned*)(Ar + 8 * AS_STR);
                a[mt][2] = *(const unsigned*)(Ar + 8);
                a[mt][3] = *(const unsigned*)(Ar + 8 * AS_STR + 8);
            }
            #pragma unroll
            for (int nt = 0; nt < NT; nt++) {
                const __nv_bfloat16* Br = Bs + (nb0 + nt * 8 + g) * AS_STR + k0 + 2 * tg;
                unsigned b0 = *(const unsigned*)(Br);
                unsigned b1 = *(const unsigned*)(Br + 8);
                mma16816(acc[0][nt], a[0], b0, b1);
                mma16816(acc[1][nt], a[1], b0, b1);
            }
        }

        // Fused epilogue: y[n] += sum over this x-block of c[n,x] * U[x,n]
        #pragma unroll
        for (int nt = 0; nt < NT; nt++) {
            int na = nb0 + nt * 8 + 2 * tg;        // thread's two n columns: na, na+1
            float p0 = 0.f, p1 = 0.f;
            #pragma unroll
            for (int mt = 0; mt < 2; mt++) {
                int x = xb * 128 + m0 + mt * 16 + g;
                p0 += __bfloat162float(Bs[na * AS_STR + x])     * acc[mt][nt][0]
                    + __bfloat162float(Bs[na * AS_STR + x + 8]) * acc[mt][nt][2];
                p1 += __bfloat162float(Bs[(na + 1) * AS_STR + x])     * acc[mt][nt][1]
                    + __bfloat162float(Bs[(na + 1) * AS_STR + x + 8]) * acc[mt][nt][3];
            }
            #pragma unroll
            for (int s = 4; s < 32; s <<= 1) {     // reduce over g (deterministic)
                p0 += __shfl_xor_sync(0xffffffffu, p0, s);
                p1 += __shfl_xor_sync(0xffffffffu, p1, s);
            }
            if (g == 0) {                          // lanes 0..3 write 8 distinct n
                ysm[wm * 128 + na]     += p0;
                ysm[wm * 128 + na + 1] += p1;
            }
        }
    }
    __syncthreads();

    // Combine 4 warp-rows, add W-part + bias, tanh, write node column h
    for (int n = tid; n < Nlev; n += 256) {
        float xvx = ysm[n] + ysm[128 + n] + ysm[256 + n] + ysm[384 + n];
        float wx = 0.f;
        #pragma unroll 4
        for (int y = 0; y < K2H; y++) wx += __bfloat162float(Bs[n * AS_STR + y]) * Wcol[y];
        g_nodes[(outBase + n) * H + h] = tanhf(xvx + wx + bias[h]);
    }
}

// ---------------------------------------------------------------------------
// Kernel 4: logits + log_softmax, one warp per node
// ---------------------------------------------------------------------------
__global__ void logits_kernel(const float* __restrict__ Wout_w,
                              const float* __restrict__ Wout_b,
                              float* __restrict__ out) {
    int node = (blockIdx.x * blockDim.x + threadIdx.x) >> 5;   // 63 blocks * 8 warps = 504
    int lane = threadIdx.x & 31;
    const float* v = g_nodes + node * H;
    float l[5];
    #pragma unroll
    for (int o = 0; o < 5; o++) {
        float p = 0.f;
        #pragma unroll
        for (int i = 0; i < 6; i++) {
            int idx = lane + 32 * i;
            p += v[idx] * Wout_w[o * H + idx];
        }
        #pragma unroll
        for (int s = 16; s; s >>= 1) p += __shfl_xor_sync(0xffffffffu, p, s);
        l[o] = p + Wout_b[o];
    }
    if (lane == 0) {
        float m = l[0];
        #pragma unroll
        for (int o = 1; o < 5; o++) m = fmaxf(m, l[o]);
        float s = 0.f;
        #pragma unroll
        for (int o = 0; o < 5; o++) s += expf(l[o] - m);
        float ls = logf(s);
        #pragma unroll
        for (int o = 0; o < 5; o++) out[node * 5 + o] = l[o] - m - ls;
    }
}

// ---------------------------------------------------------------------------
extern "C" void kernel_launch(void* const* d_in, const int* in_sizes, int n_in,
                              void* d_out, int out_size) {
    const float* embed  = (const float*)d_in[0];
    const float* Vt     = (const float*)d_in[1];
    const float* W      = (const float*)d_in[2];
    const float* b      = (const float*)d_in[3];
    const float* Wout_w = (const float*)d_in[4];
    const float* Wout_b = (const float*)d_in[5];
    const int*   leaf   = (const int*)d_in[6];
    float* out = (float*)d_out;

    const size_t SMEM = (size_t)128 * AS_STR * 2 * 2 + 512 * 4 + 384 * 4;  // 204,288 B

    cudaFuncSetAttribute(level_kernel<8>, cudaFuncAttributeMaxDynamicSharedMemorySize, (int)SMEM);
    cudaFuncSetAttribute(level_kernel<4>, cudaFuncAttributeMaxDynamicSharedMemorySize, (int)SMEM);
    cudaFuncSetAttribute(level_kernel<2>, cudaFuncAttributeMaxDynamicSharedMemorySize, (int)SMEM);
    cudaFuncSetAttribute(level_kernel<1>, cudaFuncAttributeMaxDynamicSharedMemorySize, (int)SMEM);

    convert_kernel<<<2048, 256>>>(Vt);
    leaf_kernel<<<256, H>>>(embed, leaf);

    //                         prevBase prevN outBase N
    level_kernel<8><<<192, 256, SMEM>>>(0,   32, 256, 128, W, b);
    level_kernel<4><<<192, 256, SMEM>>>(256, 16, 384,  64, W, b);
    level_kernel<2><<<192, 256, SMEM>>>(384,  8, 448,  32, W, b);
    level_kernel<1><<<192, 256, SMEM>>>(448,  4, 480,  16, W, b);
    level_kernel<1><<<192, 256, SMEM>>>(480,  2, 496,   8, W, b);

    logits_kernel<<<63, 256>>>(Wout_w, Wout_b, out);
}